// round 13
// baseline (speedup 1.0000x reference)
#include <cuda_runtime.h>
#include <cuda_fp16.h>
#include <cstdint>

// ============================================================================
// CourierEncoder fused MLP, sm_103 plain-target mma.sync FP16 path, round 13.
//   emb[B,384] -> h1 = lrelu(emb@w1+b1) -> out = lrelu(h1@w2+b2)
// fp16 operands (11-bit significand == tf32), fp32 accumulate, m16n8k16.
// INTERIOR FRONTIER POINT: CTA = 48 rows, 128 threads = 4 warps, warp tile
// 48x64 (mf=3, nf=8, 96 accs/lane), __launch_bounds__(128,3) -> 3 CTAs/SM,
// 12 warps/SM. Per-row L1 wavefronts drop ~18.5% vs R8; 3 CTAs give finer
// phase mixing. Fragment-native emb (STS.128), LDS.128 A frags, LDG.128
// fragment-blocked B, layer-2 output-column permutation -> STG.128.
// Tail: grid 5462, last CTA has 16 valid rows (clamped inputs, guarded STG).
// ============================================================================

static constexpr float NEG_SLOPEF = 0.01f;
static constexpr int KS1 = 24;   // 384/16 k-steps, layer 1
static constexpr int KS2 = 16;   // 256/16 k-steps, layer 2
static constexpr int SP1 = KS1 / 2;
static constexpr int SP2 = KS2 / 2;
static constexpr int BROWS = 262144;
static constexpr int CROWS = 48;
static constexpr int GRID  = (BROWS + CROWS - 1) / CROWS;   // 5462

// fragment-blocked fp16 weights: [n8][sp][lane] uint4
__device__ uint4 g_w1B[32 * SP1 * 32];
__device__ uint4 g_w2B[32 * SP2 * 32];

// ---- smem layout (f32 words) ----
static constexpr int SM_A1   = 0;              // 3 mt * 24 s * 32 * 4 = 9216 words
static constexpr int SM_A2   = 9216;           // 3 * 16 * 32 * 4 = 6144 words
static constexpr int SM_FR   = 15360;          // 512
static constexpr int SM_WT   = SM_FR + 512;    // 128
static constexpr int SM_BT   = SM_WT + 128;    // 128
static constexpr int SM_B1   = SM_BT + 128;    // 256
static constexpr int SM_B2   = SM_B1 + 256;    // 256
static constexpr int SM_X    = SM_B2 + 256;    // 64
static constexpr int SM_Y    = SM_X + 64;      // 64
static constexpr int SM_T    = SM_Y + 64;      // 64
static constexpr int SMEM_WORDS = SM_T + 64;
static constexpr int SMEM_BYTES = SMEM_WORDS * 4;   // 67328 B -> 3 CTAs/SM

__device__ __forceinline__ float lrelu(float v) { return v >= 0.f ? v : NEG_SLOPEF * v; }

__device__ __forceinline__ void mma16(float* c, const uint32_t* a, uint32_t b0, uint32_t b1) {
    asm volatile(
        "mma.sync.aligned.m16n8k16.row.col.f32.f16.f16.f32 "
        "{%0,%1,%2,%3}, {%4,%5,%6,%7}, {%8,%9}, {%0,%1,%2,%3};"
        : "+f"(c[0]), "+f"(c[1]), "+f"(c[2]), "+f"(c[3])
        : "r"(a[0]), "r"(a[1]), "r"(a[2]), "r"(a[3]), "r"(b0), "r"(b1));
}

__device__ __forceinline__ uint32_t pack2(float lo, float hi) {
    __half2 h = __floats2half2_rn(lo, hi);
    return *(uint32_t*)&h;
}

// ---------------------------------------------------------------- prep kernel
// w1: standard fragment-blocked layout (tile n8 covers cols [8*n8, 8*n8+8)).
// w2: OUTPUT-PERMUTED: warp covers 8 tiles (n8 = w*8 + nf); n-slot g of tile
//     nf=(2e+d) holds actual column w*64 + e*16 + 4*(g>>1) + 2d + (g&1) so
//     each thread's D values per row are 4 consecutive output columns.
__global__ void courier_prep(const float* __restrict__ w1, const float* __restrict__ w2) {
    int i = blockIdx.x * blockDim.x + threadIdx.x;
    if (i < 32 * SP1 * 32) {
        int n8 = i / (SP1 * 32);
        int rem = i % (SP1 * 32);
        int sp = rem >> 5, lane = rem & 31;
        int g = lane >> 2, tg = lane & 3;
        int n = n8 * 8 + g;
        int k0 = 32 * sp + 2 * tg;
        int k1 = k0 + 16;
        uint4 v;
        v.x = pack2(w1[(k0)      * 256 + n], w1[(k0 + 1)  * 256 + n]);
        v.y = pack2(w1[(k0 + 8)  * 256 + n], w1[(k0 + 9)  * 256 + n]);
        v.z = pack2(w1[(k1)      * 256 + n], w1[(k1 + 1)  * 256 + n]);
        v.w = pack2(w1[(k1 + 8)  * 256 + n], w1[(k1 + 9)  * 256 + n]);
        g_w1B[i] = v;
    }
    int j = i - 32 * SP1 * 32;
    if (j >= 0 && j < 32 * SP2 * 32) {
        int n8 = j / (SP2 * 32);
        int rem = j % (SP2 * 32);
        int sp = rem >> 5, lane = rem & 31;
        int g = lane >> 2, tg = lane & 3;
        int nf = n8 & 7;
        int e = nf >> 1, d = nf & 1;
        int n = (n8 >> 3) * 64 + e * 16 + 4 * (g >> 1) + 2 * d + (g & 1);
        int k0 = 32 * sp + 2 * tg;
        int k1 = k0 + 16;
        uint4 v;
        v.x = pack2(w2[(k0)      * 256 + n], w2[(k0 + 1)  * 256 + n]);
        v.y = pack2(w2[(k0 + 8)  * 256 + n], w2[(k0 + 9)  * 256 + n]);
        v.z = pack2(w2[(k1)      * 256 + n], w2[(k1 + 1)  * 256 + n]);
        v.w = pack2(w2[(k1 + 8)  * 256 + n], w2[(k1 + 9)  * 256 + n]);
        g_w2B[j] = v;
    }
}

// ---------------------------------------------------------------- gemm core
// D[48,256] += A_packed * W_blocked. Warp tile 48x64 at warp w (0..3).
template <int KS>
__device__ __forceinline__ void gemm_layer(const uint4* __restrict__ Wb,
                                           const uint4* __restrict__ smA4,
                                           int w, int lane,
                                           float acc[3][8][4]) {
    constexpr int SP = KS / 2;
    const uint4* bbase = Wb + (size_t)(w * 8) * SP * 32 + lane;

#pragma unroll
    for (int sp = 0; sp < SP; sp++) {
        uint4 bb[8];
#pragma unroll
        for (int nf = 0; nf < 8; nf++)
            bb[nf] = bbase[(nf * SP + sp) * 32];
#pragma unroll
        for (int h = 0; h < 2; h++) {
            const int s = 2 * sp + h;
            uint32_t a[3][4];
#pragma unroll
            for (int mf = 0; mf < 3; mf++) {
                uint4 av = smA4[(mf * KS + s) * 32 + lane];
                a[mf][0] = av.x; a[mf][1] = av.y; a[mf][2] = av.z; a[mf][3] = av.w;
            }
#pragma unroll
            for (int mf = 0; mf < 3; mf++)
#pragma unroll
                for (int nf = 0; nf < 8; nf++) {
                    uint32_t b0 = h ? bb[nf].z : bb[nf].x;
                    uint32_t b1 = h ? bb[nf].w : bb[nf].y;
                    mma16(acc[mf][nf], a[mf], b0, b1);
                }
        }
    }
}

// ---------------------------------------------------------------- main kernel
__global__ __launch_bounds__(128, 3)
void courier_main(const float* __restrict__ xy, const float* __restrict__ tin,
                  const float* __restrict__ w_sx, const float* __restrict__ b_sx,
                  const float* __restrict__ w_cx, const float* __restrict__ b_cx,
                  const float* __restrict__ w_sy, const float* __restrict__ b_sy,
                  const float* __restrict__ w_cy, const float* __restrict__ b_cy,
                  const float* __restrict__ w_t,  const float* __restrict__ b_t,
                  const float* __restrict__ b1,   const float* __restrict__ b2,
                  float* __restrict__ out) {
    extern __shared__ float sm[];
    uint4*  smA1 = (uint4*)(sm + SM_A1);
    uint4*  smA2 = (uint4*)(sm + SM_A2);
    float* sm_fr = sm + SM_FR;
    float* sm_wt = sm + SM_WT;
    float* sm_bt = sm + SM_BT;
    float* sm_b1 = sm + SM_B1;
    float* sm_b2 = sm + SM_B2;
    float* sm_x  = sm + SM_X;
    float* sm_y  = sm + SM_Y;
    float* sm_t  = sm + SM_T;

    const int tid  = threadIdx.x;
    const int lane = tid & 31;
    const int w    = tid >> 5;            // 0..3
    const size_t row0 = (size_t)blockIdx.x * CROWS;

    // ---- stage small params + per-row inputs (rows clamped for tail CTA) ----
    if (tid < CROWS) {
        size_t row = row0 + tid;
        if (row >= BROWS) row = BROWS - 1;
        float2 p = *(const float2*)(xy + 2 * row);
        sm_x[tid] = p.x;
        sm_y[tid] = p.y;
        sm_t[tid] = tin[row];
    }
    sm_wt[tid] = w_t[tid];
    sm_bt[tid] = b_t[tid];
    if (tid < 64) {
        sm_fr[tid]       = w_sx[tid];  sm_fr[64 + tid]  = b_sx[tid];
        sm_fr[128 + tid] = w_cx[tid];  sm_fr[192 + tid] = b_cx[tid];
        sm_fr[256 + tid] = w_sy[tid];  sm_fr[320 + tid] = b_sy[tid];
        sm_fr[384 + tid] = w_cy[tid];  sm_fr[448 + tid] = b_cy[tid];
    }
    sm_b1[tid] = b1[tid];  sm_b1[128 + tid] = b1[128 + tid];
    sm_b2[tid] = b2[tid];  sm_b2[128 + tid] = b2[128 + tid];
    __syncthreads();

    const int g = lane >> 2, tg = lane & 3;

    // ---- generate embedding A1 [48 x 384] FRAGMENT-NATIVE ----
    // warp w owns k-steps s in [6w, 6w+6), all 3 mtiles per step.
    {
        float xv0[3], xv1[3], yv0[3], yv1[3], tv0[3], tv1[3];
#pragma unroll
        for (int mt = 0; mt < 3; mt++) {
            int r0 = mt * 16 + g, r1 = r0 + 8;
            xv0[mt] = sm_x[r0]; xv1[mt] = sm_x[r1];
            yv0[mt] = sm_y[r0]; yv1[mt] = sm_y[r1];
            tv0[mt] = sm_t[r0]; tv1[mt] = sm_t[r1];
        }

        auto embval = [&](int c, float xv, float yv, float tv) -> float {
            if (c < 64)  return __sinf(fmaf(xv, sm_fr[c], sm_fr[64 + c]));
            if (c < 128) { int i = c - 64;  return __cosf(fmaf(xv, sm_fr[128 + i], sm_fr[192 + i])); }
            if (c < 192) { int i = c - 128; return __sinf(fmaf(yv, sm_fr[256 + i], sm_fr[320 + i])); }
            if (c < 256) { int i = c - 192; return __cosf(fmaf(yv, sm_fr[384 + i], sm_fr[448 + i])); }
            int i = c - 256; return lrelu(fmaf(tv, sm_wt[i], sm_bt[i]));
        };

#pragma unroll
        for (int j = 0; j < 6; j++) {
            int s = w * 6 + j;
            int k0 = 16 * s + 2 * tg;
#pragma unroll
            for (int mt = 0; mt < 3; mt++) {
                uint4 st;
                st.x = pack2(embval(k0,     xv0[mt], yv0[mt], tv0[mt]),
                             embval(k0 + 1, xv0[mt], yv0[mt], tv0[mt]));
                st.y = pack2(embval(k0,     xv1[mt], yv1[mt], tv1[mt]),
                             embval(k0 + 1, xv1[mt], yv1[mt], tv1[mt]));
                st.z = pack2(embval(k0 + 8, xv0[mt], yv0[mt], tv0[mt]),
                             embval(k0 + 9, xv0[mt], yv0[mt], tv0[mt]));
                st.w = pack2(embval(k0 + 8, xv1[mt], yv1[mt], tv1[mt]),
                             embval(k0 + 9, xv1[mt], yv1[mt], tv1[mt]));
                smA1[(mt * KS1 + s) * 32 + lane] = st;
            }
        }
    }
    __syncthreads();

    // ---- layer 1 ----
    float acc[3][8][4];
#pragma unroll
    for (int mf = 0; mf < 3; mf++)
#pragma unroll
        for (int nf = 0; nf < 8; nf++)
#pragma unroll
            for (int j = 0; j < 4; j++) acc[mf][nf][j] = 0.f;

    gemm_layer<KS1>(g_w1B, smA1, w, lane, acc);

    // ---- epilogue 1: bias + lrelu + fp16 -> A2 (separate buffer) ----
    // warp covers cols [w*64, w*64+64) -> layer-2 k-steps s2 = w*4 + e.
    {
#pragma unroll
        for (int mf = 0; mf < 3; mf++) {
#pragma unroll
            for (int e = 0; e < 4; e++) {
                int col0 = w * 64 + e * 16 + 2 * tg;
                int col1 = col0 + 8;
                uint4 st;
                st.x = pack2(lrelu(acc[mf][2*e][0]   + sm_b1[col0]),
                             lrelu(acc[mf][2*e][1]   + sm_b1[col0 + 1]));
                st.y = pack2(lrelu(acc[mf][2*e][2]   + sm_b1[col0]),
                             lrelu(acc[mf][2*e][3]   + sm_b1[col0 + 1]));
                st.z = pack2(lrelu(acc[mf][2*e+1][0] + sm_b1[col1]),
                             lrelu(acc[mf][2*e+1][1] + sm_b1[col1 + 1]));
                st.w = pack2(lrelu(acc[mf][2*e+1][2] + sm_b1[col1]),
                             lrelu(acc[mf][2*e+1][3] + sm_b1[col1 + 1]));
                int s2 = w * 4 + e;
                smA2[(mf * KS2 + s2) * 32 + lane] = st;
            }
        }
    }
    __syncthreads();

    // ---- layer 2 (w2 columns permuted in prep) ----
#pragma unroll
    for (int mf = 0; mf < 3; mf++)
#pragma unroll
        for (int nf = 0; nf < 8; nf++)
#pragma unroll
            for (int j = 0; j < 4; j++) acc[mf][nf][j] = 0.f;

    gemm_layer<KS2>(g_w2B, smA2, w, lane, acc);

    // ---- final epilogue: bias + lrelu, aligned STG.128 (guarded for tail) ----
    {
        float* obase = out + row0 * 256;
#pragma unroll
        for (int mf = 0; mf < 3; mf++) {
            int r0 = mf * 16 + g;
            bool ok0 = (row0 + r0     < BROWS);
            bool ok1 = (row0 + r0 + 8 < BROWS);
#pragma unroll
            for (int e = 0; e < 4; e++) {
                int c = w * 64 + e * 16 + 4 * tg;
                float4 bv = *(const float4*)(sm_b2 + c);
                float4 v0, v1;
                v0.x = lrelu(acc[mf][2*e][0]   + bv.x);
                v0.y = lrelu(acc[mf][2*e][1]   + bv.y);
                v0.z = lrelu(acc[mf][2*e+1][0] + bv.z);
                v0.w = lrelu(acc[mf][2*e+1][1] + bv.w);
                v1.x = lrelu(acc[mf][2*e][2]   + bv.x);
                v1.y = lrelu(acc[mf][2*e][3]   + bv.y);
                v1.z = lrelu(acc[mf][2*e+1][2] + bv.z);
                v1.w = lrelu(acc[mf][2*e+1][3] + bv.w);
                if (ok0) *(float4*)(obase + r0 * 256 + c)       = v0;
                if (ok1) *(float4*)(obase + (r0 + 8) * 256 + c) = v1;
            }
        }
    }
}

// ---------------------------------------------------------------- launcher
extern "C" void kernel_launch(void* const* d_in, const int* in_sizes, int n_in,
                              void* d_out, int out_size) {
    const float* xy   = (const float*)d_in[0];
    const float* t    = (const float*)d_in[1];
    const float* w_sx = (const float*)d_in[2];
    const float* b_sx = (const float*)d_in[3];
    const float* w_cx = (const float*)d_in[4];
    const float* b_cx = (const float*)d_in[5];
    const float* w_sy = (const float*)d_in[6];
    const float* b_sy = (const float*)d_in[7];
    const float* w_cy = (const float*)d_in[8];
    const float* b_cy = (const float*)d_in[9];
    const float* w_t  = (const float*)d_in[10];
    const float* b_t  = (const float*)d_in[11];
    const float* w1   = (const float*)d_in[12];
    const float* b1   = (const float*)d_in[13];
    const float* w2   = (const float*)d_in[14];
    const float* b2   = (const float*)d_in[15];
    float* out = (float*)d_out;

    courier_prep<<<128, 256>>>(w1, w2);

    static bool attr_set = false;
    if (!attr_set) {
        cudaFuncSetAttribute(courier_main, cudaFuncAttributeMaxDynamicSharedMemorySize,
                             SMEM_BYTES);
        attr_set = true;
    }

    courier_main<<<GRID, 128, SMEM_BYTES>>>(xy, t, w_sx, b_sx, w_cx, b_cx,
                                            w_sy, b_sy, w_cy, b_cy,
                                            w_t, b_t, b1, b2, out);
}

// round 16
// speedup vs baseline: 1.7526x; 1.7526x over previous
#include <cuda_runtime.h>
#include <cuda_fp16.h>
#include <cstdint>

// ============================================================================
// CourierEncoder fused MLP, sm_103 plain-target mma.sync FP16 path, round 14.
//   emb[B,384] -> h1 = lrelu(emb@w1+b1) -> out = lrelu(h1@w2+b2)
// fp16 operands (11-bit significand == tf32), fp32 accumulate, m16n8k16.
// == R12 (best: 231.6us) + LOW-LDS EMBEDDING ==
// CTA = 64 rows, 256 threads = 8 warps in 1(M64) x 8(N32) grid; 2 CTAs/SM.
// Warp tile 64x32: mf=4, nf=4, 64 accs/lane (regs == 128 == 64K/512 exactly).
// Emb: warp w owns k-steps {3w,3w+1,3w+2} x all 4 mtiles; per-step freq
// consts hoisted into registers (8 LDS) and reused across 8 rows ->
// ~48 LDS/warp instead of ~192. Identical arithmetic to R12.
// LDS.128 A frags, LDG.128 fragment-blocked B (distance-1 double buffer),
// layer-2 output-column permutation -> aligned STG.128 epilogue.
// ============================================================================

static constexpr float NEG_SLOPEF = 0.01f;
static constexpr int KS1 = 24;   // 384/16 k-steps, layer 1
static constexpr int KS2 = 16;   // 256/16 k-steps, layer 2
static constexpr int SP1 = KS1 / 2;
static constexpr int SP2 = KS2 / 2;

// fragment-blocked fp16 weights: [n8][sp][lane] uint4 = {b0(2sp),b1(2sp),b0(2sp+1),b1(2sp+1)}
__device__ uint4 g_w1B[32 * SP1 * 32];
__device__ uint4 g_w2B[32 * SP2 * 32];

// ---- smem layout (f32 words) ----
static constexpr int SM_A1   = 0;            // 3072 uint4 = 12288 words
static constexpr int SM_A2   = 12288;        // 2048 uint4 =  8192 words
static constexpr int SM_FR   = 20480;
static constexpr int SM_WT   = SM_FR + 512;
static constexpr int SM_BT   = SM_WT + 128;
static constexpr int SM_B1   = SM_BT + 128;
static constexpr int SM_B2   = SM_B1 + 256;
static constexpr int SM_X    = SM_B2 + 256;
static constexpr int SM_Y    = SM_X + 64;
static constexpr int SM_T    = SM_Y + 64;
static constexpr int SMEM_WORDS = SM_T + 64;
static constexpr int SMEM_BYTES = SMEM_WORDS * 4;   // ~86 KB -> 2 CTAs/SM

__device__ __forceinline__ float lrelu(float v) { return v >= 0.f ? v : NEG_SLOPEF * v; }

__device__ __forceinline__ void mma16(float* c, const uint32_t* a, uint32_t b0, uint32_t b1) {
    asm volatile(
        "mma.sync.aligned.m16n8k16.row.col.f32.f16.f16.f32 "
        "{%0,%1,%2,%3}, {%4,%5,%6,%7}, {%8,%9}, {%0,%1,%2,%3};"
        : "+f"(c[0]), "+f"(c[1]), "+f"(c[2]), "+f"(c[3])
        : "r"(a[0]), "r"(a[1]), "r"(a[2]), "r"(a[3]), "r"(b0), "r"(b1));
}

__device__ __forceinline__ uint32_t pack2(float lo, float hi) {
    __half2 h = __floats2half2_rn(lo, hi);
    return *(uint32_t*)&h;
}

// ---------------------------------------------------------------- prep kernel
__global__ void courier_prep(const float* __restrict__ w1, const float* __restrict__ w2) {
    int i = blockIdx.x * blockDim.x + threadIdx.x;
    if (i < 32 * SP1 * 32) {
        int n8 = i / (SP1 * 32);
        int rem = i % (SP1 * 32);
        int sp = rem >> 5, lane = rem & 31;
        int g = lane >> 2, tg = lane & 3;
        int n = n8 * 8 + g;
        int k0 = 32 * sp + 2 * tg;
        int k1 = k0 + 16;
        uint4 v;
        v.x = pack2(w1[(k0)      * 256 + n], w1[(k0 + 1)  * 256 + n]);
        v.y = pack2(w1[(k0 + 8)  * 256 + n], w1[(k0 + 9)  * 256 + n]);
        v.z = pack2(w1[(k1)      * 256 + n], w1[(k1 + 1)  * 256 + n]);
        v.w = pack2(w1[(k1 + 8)  * 256 + n], w1[(k1 + 9)  * 256 + n]);
        g_w1B[i] = v;
    }
    int j = i - 32 * SP1 * 32;
    if (j >= 0 && j < 32 * SP2 * 32) {
        int n8 = j / (SP2 * 32);
        int rem = j % (SP2 * 32);
        int sp = rem >> 5, lane = rem & 31;
        int g = lane >> 2, tg = lane & 3;
        // Output-column permutation: frag n-slot g of tile nf=(2e+d) holds
        // actual column warpbase + 16e + 4*(g>>1) + 2d + (g&1).
        int nf = n8 & 3;
        int e = nf >> 1, d = nf & 1;
        int n = (n8 >> 2) * 32 + e * 16 + 4 * (g >> 1) + 2 * d + (g & 1);
        int k0 = 32 * sp + 2 * tg;
        int k1 = k0 + 16;
        uint4 v;
        v.x = pack2(w2[(k0)      * 256 + n], w2[(k0 + 1)  * 256 + n]);
        v.y = pack2(w2[(k0 + 8)  * 256 + n], w2[(k0 + 9)  * 256 + n]);
        v.z = pack2(w2[(k1)      * 256 + n], w2[(k1 + 1)  * 256 + n]);
        v.w = pack2(w2[(k1 + 8)  * 256 + n], w2[(k1 + 9)  * 256 + n]);
        g_w2B[j] = v;
    }
}

// ---------------------------------------------------------------- gemm core
template <int KS>
__device__ __forceinline__ void gemm_layer(const uint4* __restrict__ Wb,
                                           const uint4* __restrict__ smA4,
                                           int warp_n, int lane,
                                           float acc[4][4][4]) {
    constexpr int SP = KS / 2;
    const uint4* bptr[4];
#pragma unroll
    for (int nf = 0; nf < 4; nf++)
        bptr[nf] = Wb + (size_t)((warp_n * 4 + nf) * SP) * 32 + lane;

    uint4 bb[2][4];
#pragma unroll
    for (int nf = 0; nf < 4; nf++) bb[0][nf] = bptr[nf][0];

#pragma unroll
    for (int sp = 0; sp < SP; sp++) {
        const int cur = sp & 1;
        if (sp + 1 < SP) {
#pragma unroll
            for (int nf = 0; nf < 4; nf++)
                bb[cur ^ 1][nf] = bptr[nf][(sp + 1) * 32];
        }
#pragma unroll
        for (int h = 0; h < 2; h++) {
            const int s = 2 * sp + h;
            uint32_t a[4][4];
#pragma unroll
            for (int mf = 0; mf < 4; mf++) {
                uint4 av = smA4[(mf * KS + s) * 32 + lane];
                a[mf][0] = av.x; a[mf][1] = av.y; a[mf][2] = av.z; a[mf][3] = av.w;
            }
#pragma unroll
            for (int mf = 0; mf < 4; mf++)
#pragma unroll
                for (int nf = 0; nf < 4; nf++) {
                    uint32_t b0 = h ? bb[cur][nf].z : bb[cur][nf].x;
                    uint32_t b1 = h ? bb[cur][nf].w : bb[cur][nf].y;
                    mma16(acc[mf][nf], a[mf], b0, b1);
                }
        }
    }
}

// ---------------------------------------------------------------- main kernel
__global__ __launch_bounds__(256, 2)
void courier_main(const float* __restrict__ xy, const float* __restrict__ tin,
                  const float* __restrict__ w_sx, const float* __restrict__ b_sx,
                  const float* __restrict__ w_cx, const float* __restrict__ b_cx,
                  const float* __restrict__ w_sy, const float* __restrict__ b_sy,
                  const float* __restrict__ w_cy, const float* __restrict__ b_cy,
                  const float* __restrict__ w_t,  const float* __restrict__ b_t,
                  const float* __restrict__ b1,   const float* __restrict__ b2,
                  float* __restrict__ out) {
    extern __shared__ float sm[];
    uint4*  smA1 = (uint4*)(sm + SM_A1);
    uint4*  smA2 = (uint4*)(sm + SM_A2);
    float* sm_fr = sm + SM_FR;
    float* sm_wt = sm + SM_WT;
    float* sm_bt = sm + SM_BT;
    float* sm_b1 = sm + SM_B1;
    float* sm_b2 = sm + SM_B2;
    float* sm_x  = sm + SM_X;
    float* sm_y  = sm + SM_Y;
    float* sm_t  = sm + SM_T;

    const int tid    = threadIdx.x;
    const int lane   = tid & 31;
    const int warp_n = tid >> 5;          // 0..7

    // ---- stage small params + per-row inputs ----
    if (tid < 64) {
        int row = blockIdx.x * 64 + tid;
        float2 p = *(const float2*)(xy + 2 * row);
        sm_x[tid] = p.x;
        sm_y[tid] = p.y;
        sm_t[tid] = tin[row];
    }
    if (tid < 128) {
        sm_wt[tid] = w_t[tid];
        sm_bt[tid] = b_t[tid];
    }
    if (tid < 64) {
        sm_fr[tid]       = w_sx[tid];  sm_fr[64 + tid]  = b_sx[tid];
        sm_fr[128 + tid] = w_cx[tid];  sm_fr[192 + tid] = b_cx[tid];
        sm_fr[256 + tid] = w_sy[tid];  sm_fr[320 + tid] = b_sy[tid];
        sm_fr[384 + tid] = w_cy[tid];  sm_fr[448 + tid] = b_cy[tid];
    }
    sm_b1[tid] = b1[tid];
    sm_b2[tid] = b2[tid];
    __syncthreads();

    // ---- generate embedding A1 [64 x 384] FRAGMENT-NATIVE, LOW-LDS ----
    // warp w owns k-steps s in {3w, 3w+1, 3w+2}, all 4 mtiles per step.
    // Per step: 4 (w,b) freq pairs hoisted to regs (8 LDS), reused over 8 rows.
    // Values/layout bit-identical to R12's emb.
    {
        const int g = lane >> 2, tg = lane & 3;
#pragma unroll
        for (int js = 0; js < 3; js++) {
            const int s  = 3 * warp_n + js;
            const int k0 = 16 * s + 2 * tg;
            const bool isT    = (s >= 16);
            const bool useCos = ((s >> 2) & 1);
            float wA, wB, wC, wD, bA, bB, bC, bD;
            const float* inp;
            if (isT) {
                int i = k0 - 256;
                wA = sm_wt[i];     wB = sm_wt[i + 1];
                wC = sm_wt[i + 8]; wD = sm_wt[i + 9];
                bA = sm_bt[i];     bB = sm_bt[i + 1];
                bC = sm_bt[i + 8]; bD = sm_bt[i + 9];
                inp = sm_t;
            } else {
                // k<256: w = fr[k + 64*R], b = fr[k + 64*(R+1)], R = s>>2
                int base = k0 + 64 * (s >> 2);
                wA = sm_fr[base];      wB = sm_fr[base + 1];
                wC = sm_fr[base + 8];  wD = sm_fr[base + 9];
                bA = sm_fr[base + 64]; bB = sm_fr[base + 65];
                bC = sm_fr[base + 72]; bD = sm_fr[base + 73];
                inp = (s >= 8) ? sm_y : sm_x;
            }
#pragma unroll
            for (int mt = 0; mt < 4; mt++) {
                int r0 = mt * 16 + g;
                float in0 = inp[r0], in1 = inp[r0 + 8];
                float aA0 = fmaf(in0, wA, bA), aB0 = fmaf(in0, wB, bB);
                float aC0 = fmaf(in0, wC, bC), aD0 = fmaf(in0, wD, bD);
                float aA1 = fmaf(in1, wA, bA), aB1 = fmaf(in1, wB, bB);
                float aC1 = fmaf(in1, wC, bC), aD1 = fmaf(in1, wD, bD);
                float vA0, vB0, vC0, vD0, vA1, vB1, vC1, vD1;
                if (isT) {
                    vA0 = lrelu(aA0); vB0 = lrelu(aB0);
                    vC0 = lrelu(aC0); vD0 = lrelu(aD0);
                    vA1 = lrelu(aA1); vB1 = lrelu(aB1);
                    vC1 = lrelu(aC1); vD1 = lrelu(aD1);
                } else if (useCos) {
                    vA0 = __cosf(aA0); vB0 = __cosf(aB0);
                    vC0 = __cosf(aC0); vD0 = __cosf(aD0);
                    vA1 = __cosf(aA1); vB1 = __cosf(aB1);
                    vC1 = __cosf(aC1); vD1 = __cosf(aD1);
                } else {
                    vA0 = __sinf(aA0); vB0 = __sinf(aB0);
                    vC0 = __sinf(aC0); vD0 = __sinf(aD0);
                    vA1 = __sinf(aA1); vB1 = __sinf(aB1);
                    vC1 = __sinf(aC1); vD1 = __sinf(aD1);
                }
                uint4 st;
                st.x = pack2(vA0, vB0);
                st.y = pack2(vA1, vB1);
                st.z = pack2(vC0, vD0);
                st.w = pack2(vC1, vD1);
                smA1[(mt * KS1 + s) * 32 + lane] = st;
            }
        }
    }
    __syncthreads();

    // ---- layer 1 ----
    float acc[4][4][4];
#pragma unroll
    for (int mf = 0; mf < 4; mf++)
#pragma unroll
        for (int nf = 0; nf < 4; nf++)
#pragma unroll
            for (int j = 0; j < 4; j++) acc[mf][nf][j] = 0.f;

    gemm_layer<KS1>(g_w1B, smA1, warp_n, lane, acc);

    // ---- epilogue 1: bias + lrelu + fp16 -> A2 (separate buffer, no WAR sync) ----
    {
        const int tg = lane & 3;
#pragma unroll
        for (int mf = 0; mf < 4; mf++) {
#pragma unroll
            for (int e = 0; e < 2; e++) {
                int col0 = warp_n * 32 + (2 * e) * 8 + 2 * tg;
                int col1 = col0 + 8;
                uint4 st;
                st.x = pack2(lrelu(acc[mf][2*e][0]   + sm_b1[col0]),
                             lrelu(acc[mf][2*e][1]   + sm_b1[col0 + 1]));
                st.y = pack2(lrelu(acc[mf][2*e][2]   + sm_b1[col0]),
                             lrelu(acc[mf][2*e][3]   + sm_b1[col0 + 1]));
                st.z = pack2(lrelu(acc[mf][2*e+1][0] + sm_b1[col1]),
                             lrelu(acc[mf][2*e+1][1] + sm_b1[col1 + 1]));
                st.w = pack2(lrelu(acc[mf][2*e+1][2] + sm_b1[col1]),
                             lrelu(acc[mf][2*e+1][3] + sm_b1[col1 + 1]));
                int s2 = warp_n * 2 + e;
                smA2[(mf * KS2 + s2) * 32 + lane] = st;
            }
        }
    }
    __syncthreads();

    // ---- layer 2 (w2 columns permuted in prep) ----
#pragma unroll
    for (int mf = 0; mf < 4; mf++)
#pragma unroll
        for (int nf = 0; nf < 4; nf++)
#pragma unroll
            for (int j = 0; j < 4; j++) acc[mf][nf][j] = 0.f;

    gemm_layer<KS2>(g_w2B, smA2, warp_n, lane, acc);

    // ---- final epilogue: bias + lrelu, aligned STG.128 ----
    {
        const int g  = lane >> 2;
        const int tg = lane & 3;
        float* obase = out + (size_t)blockIdx.x * 64 * 256;
#pragma unroll
        for (int mf = 0; mf < 4; mf++) {
            int r0 = mf * 16 + g;
#pragma unroll
            for (int e = 0; e < 2; e++) {
                int c = warp_n * 32 + e * 16 + 4 * tg;
                float4 v0, v1;
                v0.x = lrelu(acc[mf][2*e][0]   + sm_b2[c]);
                v0.y = lrelu(acc[mf][2*e][1]   + sm_b2[c + 1]);
                v0.z = lrelu(acc[mf][2*e+1][0] + sm_b2[c + 2]);
                v0.w = lrelu(acc[mf][2*e+1][1] + sm_b2[c + 3]);
                v1.x = lrelu(acc[mf][2*e][2]   + sm_b2[c]);
                v1.y = lrelu(acc[mf][2*e][3]   + sm_b2[c + 1]);
                v1.z = lrelu(acc[mf][2*e+1][2] + sm_b2[c + 2]);
                v1.w = lrelu(acc[mf][2*e+1][3] + sm_b2[c + 3]);
                *(float4*)(obase + r0 * 256 + c)       = v0;
                *(float4*)(obase + (r0 + 8) * 256 + c) = v1;
            }
        }
    }
}

// ---------------------------------------------------------------- launcher
extern "C" void kernel_launch(void* const* d_in, const int* in_sizes, int n_in,
                              void* d_out, int out_size) {
    const float* xy   = (const float*)d_in[0];
    const float* t    = (const float*)d_in[1];
    const float* w_sx = (const float*)d_in[2];
    const float* b_sx = (const float*)d_in[3];
    const float* w_cx = (const float*)d_in[4];
    const float* b_cx = (const float*)d_in[5];
    const float* w_sy = (const float*)d_in[6];
    const float* b_sy = (const float*)d_in[7];
    const float* w_cy = (const float*)d_in[8];
    const float* b_cy = (const float*)d_in[9];
    const float* w_t  = (const float*)d_in[10];
    const float* b_t  = (const float*)d_in[11];
    const float* w1   = (const float*)d_in[12];
    const float* b1   = (const float*)d_in[13];
    const float* w2   = (const float*)d_in[14];
    const float* b2   = (const float*)d_in[15];
    float* out = (float*)d_out;

    courier_prep<<<80, 256>>>(w1, w2);

    static bool attr_set = false;
    if (!attr_set) {
        cudaFuncSetAttribute(courier_main, cudaFuncAttributeMaxDynamicSharedMemorySize,
                             SMEM_BYTES);
        attr_set = true;
    }

    courier_main<<<4096, 256, SMEM_BYTES>>>(xy, t, w_sx, b_sx, w_cx, b_cx,
                                            w_sy, b_sy, w_cy, b_cy,
                                            w_t, b_t, b1, b2, out);
}